// round 2
// baseline (speedup 1.0000x reference)
#include <cuda_runtime.h>

// Problem constants
#define NB 16       // batch
#define NC 256      // channels (DIM)
#define NS 4096     // spatial n = 64*64
#define NH 512      // hidden = heads*dim_head
#define NHEADS 8
#define NSPLIT 8
#define KCHUNK (NS / NSPLIT)   // 512

typedef unsigned long long u64;

// ---------------- scratch (static device memory; no allocations) -------------
__device__ float g_Gpart[NSPLIT][NB][NC][NC];  // 32 MB split-K partials
__device__ float g_G[NB][NC][NC];              // 4 MB  Gram matrices
__device__ float g_QG[NB][NH][NC];             // 8 MB  Wq * G
__device__ float g_M[NB][NH][NC];              // 8 MB  attn * Wv
__device__ float g_P[NB][NC][NC];              // 4 MB  W_out * M

// ---------------- packed fp32x2 helpers (Blackwell FFMA2) --------------------
__device__ __forceinline__ u64 pack2_dup(float v) {
    u64 r;
    asm("mov.b64 %0, {%1, %1};" : "=l"(r) : "f"(v));
    return r;
}
__device__ __forceinline__ void fma2(u64& d, u64 a, u64 b) {
    asm("fma.rn.f32x2 %0, %1, %2, %0;" : "+l"(d) : "l"(a), "l"(b));
}
__device__ __forceinline__ void unpack2(float& lo, float& hi, u64 v) {
    asm("mov.b64 {%0, %1}, %2;" : "=f"(lo), "=f"(hi) : "l"(v));
}

// =============================================================================
// Kernel 1: Gram partials.  Gpart[s][b] = X[b][:, ks] * X[b][:, ks]^T
// 128x128 tile per CTA, 256 threads, 8x8 micro-tile (packed as 8x4 f32x2).
// grid = (4 tiles, NSPLIT, NB)
// =============================================================================
__global__ __launch_bounds__(256) void gram_kernel(const float* __restrict__ x) {
    const int bi = blockIdx.x >> 1, bj = blockIdx.x & 1;
    const int s = blockIdx.y, b = blockIdx.z;
    const float* Xb = x + (size_t)b * NC * NS;

    __shared__ __align__(16) float As[16][132];
    __shared__ __align__(16) float Bs[16][132];

    const int tid = threadIdx.x, tx = tid & 15, ty = tid >> 4;
    u64 acc[8][4];
    const u64 z = 0ull;
#pragma unroll
    for (int i = 0; i < 8; i++)
#pragma unroll
        for (int jp = 0; jp < 4; jp++) acc[i][jp] = z;

    const int k0 = s * KCHUNK;
    for (int kt = k0; kt < k0 + KCHUNK; kt += 16) {
#pragma unroll
        for (int it = 0; it < 2; it++) {
            int idx = it * 256 + tid;
            int row = idx >> 2, k4 = idx & 3;
            float4 v = *(const float4*)(Xb + (size_t)(bi * 128 + row) * NS + kt + k4 * 4);
            As[k4 * 4 + 0][row] = v.x; As[k4 * 4 + 1][row] = v.y;
            As[k4 * 4 + 2][row] = v.z; As[k4 * 4 + 3][row] = v.w;
            float4 u = *(const float4*)(Xb + (size_t)(bj * 128 + row) * NS + kt + k4 * 4);
            Bs[k4 * 4 + 0][row] = u.x; Bs[k4 * 4 + 1][row] = u.y;
            Bs[k4 * 4 + 2][row] = u.z; Bs[k4 * 4 + 3][row] = u.w;
        }
        __syncthreads();
#pragma unroll
        for (int kk = 0; kk < 16; kk++) {
            u64 aP[8], bP[4];
#pragma unroll
            for (int i = 0; i < 8; i++) aP[i] = pack2_dup(As[kk][ty + 16 * i]);
#pragma unroll
            for (int jp = 0; jp < 4; jp++)
                bP[jp] = *(const u64*)(&Bs[kk][tx * 2 + 32 * jp]);
#pragma unroll
            for (int i = 0; i < 8; i++)
#pragma unroll
                for (int jp = 0; jp < 4; jp++) fma2(acc[i][jp], aP[i], bP[jp]);
        }
        __syncthreads();
    }

    float* Gp = &g_Gpart[s][b][0][0];
#pragma unroll
    for (int i = 0; i < 8; i++) {
        int r = bi * 128 + ty + 16 * i;
#pragma unroll
        for (int jp = 0; jp < 4; jp++) {
            float lo, hi;
            unpack2(lo, hi, acc[i][jp]);
            float2 o; o.x = lo; o.y = hi;
            *(float2*)&Gp[(size_t)r * NC + bj * 128 + tx * 2 + 32 * jp] = o;
        }
    }
}

// =============================================================================
// Kernel 2: deterministic split-K reduction.  G = sum_s Gpart[s]
// =============================================================================
__global__ __launch_bounds__(256) void reduce_g_kernel() {
    int i = blockIdx.x * blockDim.x + threadIdx.x;   // float4 index, 262144 total
    const float4* p = (const float4*)g_Gpart;
    const int stride = NB * NC * NC / 4;
    float4 sum = make_float4(0.f, 0.f, 0.f, 0.f);
#pragma unroll
    for (int s = 0; s < NSPLIT; s++) {
        float4 v = p[(size_t)s * stride + i];
        sum.x += v.x; sum.y += v.y; sum.z += v.z; sum.w += v.w;
    }
    ((float4*)g_G)[i] = sum;
}

// =============================================================================
// Kernel 3/5: batched 64x64-tile SGEMM.
// MODE 0: QG[b] = Wq(=w_qkv rows 0..511) * G[b]      (K=256), grid (4,8,NB)
// MODE 1: P[b]  = W_out * M[b]                       (K=512), grid (4,4,NB)
// =============================================================================
template <int MODE>
__global__ __launch_bounds__(256) void gemm64_kernel(const float* __restrict__ W) {
    const int nt = blockIdx.x, mt = blockIdx.y, b = blockIdx.z;
    const int K = (MODE == 0) ? 256 : 512;
    const int N = 256;
    const float* Ab = W;
    const float* Bb = (MODE == 0) ? &g_G[b][0][0] : &g_M[b][0][0];
    float* Cb = (MODE == 0) ? &g_QG[b][0][0] : &g_P[b][0][0];

    __shared__ __align__(16) float As[16][65];
    __shared__ __align__(16) float Bs[16][68];
    const int tid = threadIdx.x, tx = tid & 15, ty = tid >> 4;
    float acc[4][4] = {};

    for (int kt = 0; kt < K; kt += 16) {
        {
            int row = tid >> 2, k4 = tid & 3;
            float4 v = *(const float4*)(Ab + (size_t)(mt * 64 + row) * K + kt + k4 * 4);
            As[k4 * 4 + 0][row] = v.x; As[k4 * 4 + 1][row] = v.y;
            As[k4 * 4 + 2][row] = v.z; As[k4 * 4 + 3][row] = v.w;
            int kb = tid >> 4, n4 = tid & 15;
            *(float4*)&Bs[kb][n4 * 4] =
                *(const float4*)(Bb + (size_t)(kt + kb) * N + nt * 64 + n4 * 4);
        }
        __syncthreads();
#pragma unroll
        for (int kk = 0; kk < 16; kk++) {
            float a[4], bb[4];
#pragma unroll
            for (int i = 0; i < 4; i++) a[i] = As[kk][ty + 16 * i];
#pragma unroll
            for (int j = 0; j < 4; j++) bb[j] = Bs[kk][tx + 16 * j];
#pragma unroll
            for (int i = 0; i < 4; i++)
#pragma unroll
                for (int j = 0; j < 4; j++) acc[i][j] += a[i] * bb[j];
        }
        __syncthreads();
    }
#pragma unroll
    for (int i = 0; i < 4; i++)
#pragma unroll
        for (int j = 0; j < 4; j++)
            Cb[(size_t)(mt * 64 + ty + 16 * i) * N + nt * 64 + tx + 16 * j] = acc[i][j];
}

// =============================================================================
// Kernel 4: per-(batch,head) attention core.
//   sim = scale * QG_h * Wk_h^T  (64x64, K=256)  -> softmax rows
//   M_h = attn * Wv_h            (64x256)
// grid = (NHEADS, NB), 256 threads
// =============================================================================
__global__ __launch_bounds__(256) void attn_kernel(const float* __restrict__ wqkv) {
    const int h = blockIdx.x, b = blockIdx.y;
    __shared__ float S[64][65];
    __shared__ __align__(16) float Buf[4160];
    const int tid = threadIdx.x, tx = tid & 15, ty = tid >> 4;

    const float* QGb = &g_QG[b][h * 64][0];
    const float* Wk = wqkv + (size_t)(NH + h * 64) * NC;
    const float* Wv = wqkv + (size_t)(2 * NH + h * 64) * NC;
    float* Qs = Buf;            // [64][32]
    float* Ks = Buf + 64 * 32;  // [32][65] (transposed, padded)

    float acc[4][4] = {};
    for (int kc = 0; kc < NC; kc += 32) {
#pragma unroll
        for (int it = 0; it < 2; it++) {
            int idx = it * 256 + tid;
            int row = idx >> 3, c4 = idx & 7;
            *(float4*)&Qs[row * 32 + c4 * 4] =
                *(const float4*)(QGb + (size_t)row * NC + kc + c4 * 4);
            float4 v = *(const float4*)(Wk + (size_t)row * NC + kc + c4 * 4);
            Ks[(c4 * 4 + 0) * 65 + row] = v.x;
            Ks[(c4 * 4 + 1) * 65 + row] = v.y;
            Ks[(c4 * 4 + 2) * 65 + row] = v.z;
            Ks[(c4 * 4 + 3) * 65 + row] = v.w;
        }
        __syncthreads();
#pragma unroll
        for (int kk = 0; kk < 32; kk++) {
            float a[4], bb[4];
#pragma unroll
            for (int i = 0; i < 4; i++) a[i] = Qs[(ty + 16 * i) * 32 + kk];
#pragma unroll
            for (int j = 0; j < 4; j++) bb[j] = Ks[kk * 65 + tx + 16 * j];
#pragma unroll
            for (int i = 0; i < 4; i++)
#pragma unroll
                for (int j = 0; j < 4; j++) acc[i][j] += a[i] * bb[j];
        }
        __syncthreads();
    }
    const float scale = 0.125f;  // 64^-0.5
#pragma unroll
    for (int i = 0; i < 4; i++)
#pragma unroll
        for (int j = 0; j < 4; j++)
            S[ty + 16 * i][tx + 16 * j] = acc[i][j] * scale;
    __syncthreads();

    if (tid < 64) {
        float m = -1e30f;
        for (int j = 0; j < 64; j++) m = fmaxf(m, S[tid][j]);
        float sum = 0.f;
        for (int j = 0; j < 64; j++) {
            float e = expf(S[tid][j] - m);
            S[tid][j] = e;
            sum += e;
        }
        float inv = 1.f / sum;
        for (int j = 0; j < 64; j++) S[tid][j] *= inv;
    }
    __syncthreads();

    float* Ms = &g_M[b][h * 64][0];
    float* Vs = Buf;  // [64][64]
    for (int cc = 0; cc < NC; cc += 64) {
#pragma unroll
        for (int it = 0; it < 4; it++) {
            int idx = it * 256 + tid;
            int row = idx >> 4, c4 = idx & 15;
            *(float4*)&Vs[row * 64 + c4 * 4] =
                *(const float4*)(Wv + (size_t)row * NC + cc + c4 * 4);
        }
        __syncthreads();
        float o[4][4] = {};
        for (int j = 0; j < 64; j++) {
            float a[4], vv[4];
#pragma unroll
            for (int i = 0; i < 4; i++) a[i] = S[ty + 16 * i][j];
#pragma unroll
            for (int jj = 0; jj < 4; jj++) vv[jj] = Vs[j * 64 + tx + 16 * jj];
#pragma unroll
            for (int i = 0; i < 4; i++)
#pragma unroll
                for (int jj = 0; jj < 4; jj++) o[i][jj] += a[i] * vv[jj];
        }
#pragma unroll
        for (int i = 0; i < 4; i++)
#pragma unroll
            for (int jj = 0; jj < 4; jj++)
                Ms[(size_t)(ty + 16 * i) * NC + cc + tx + 16 * jj] = o[i][jj];
        __syncthreads();
    }
}

// =============================================================================
// Kernel 6: final = P[b] * X[b] + bias  -> d_out.  128x128 tiles, f32x2 inner.
// grid = (32, 2, NB)
// =============================================================================
__global__ __launch_bounds__(256) void final_kernel(const float* __restrict__ x,
                                                    const float* __restrict__ bias,
                                                    float* __restrict__ out) {
    const int nt = blockIdx.x, mt = blockIdx.y, b = blockIdx.z;
    const float* Pb = &g_P[b][0][0];
    const float* Xb = x + (size_t)b * NC * NS;

    __shared__ __align__(16) float As[16][132];
    __shared__ __align__(16) float Bs[16][132];
    const int tid = threadIdx.x, tx = tid & 15, ty = tid >> 4;

    u64 acc[8][4];
#pragma unroll
    for (int i = 0; i < 8; i++)
#pragma unroll
        for (int jp = 0; jp < 4; jp++) acc[i][jp] = 0ull;

    for (int kt = 0; kt < NC; kt += 16) {
#pragma unroll
        for (int it = 0; it < 2; it++) {
            int idx = it * 256 + tid;
            int row = idx >> 2, k4 = idx & 3;
            float4 v = *(const float4*)(Pb + (size_t)(mt * 128 + row) * NC + kt + k4 * 4);
            As[k4 * 4 + 0][row] = v.x; As[k4 * 4 + 1][row] = v.y;
            As[k4 * 4 + 2][row] = v.z; As[k4 * 4 + 3][row] = v.w;
            int k = idx >> 5, n4 = idx & 31;
            *(float4*)&Bs[k][n4 * 4] =
                *(const float4*)(Xb + (size_t)(kt + k) * NS + nt * 128 + n4 * 4);
        }
        __syncthreads();
#pragma unroll
        for (int kk = 0; kk < 16; kk++) {
            u64 aP[8], bP[4];
#pragma unroll
            for (int i = 0; i < 8; i++) aP[i] = pack2_dup(As[kk][ty + 16 * i]);
#pragma unroll
            for (int jp = 0; jp < 4; jp++)
                bP[jp] = *(const u64*)(&Bs[kk][tx * 2 + 32 * jp]);
#pragma unroll
            for (int i = 0; i < 8; i++)
#pragma unroll
                for (int jp = 0; jp < 4; jp++) fma2(acc[i][jp], aP[i], bP[jp]);
        }
        __syncthreads();
    }

#pragma unroll
    for (int i = 0; i < 8; i++) {
        int o = mt * 128 + ty + 16 * i;
        float bv = bias[o];
#pragma unroll
        for (int jp = 0; jp < 4; jp++) {
            float lo, hi;
            unpack2(lo, hi, acc[i][jp]);
            float2 w; w.x = lo + bv; w.y = hi + bv;
            *(float2*)&out[((size_t)b * NC + o) * NS + nt * 128 + tx * 2 + 32 * jp] = w;
        }
    }
}

// =============================================================================
extern "C" void kernel_launch(void* const* d_in, const int* in_sizes, int n_in,
                              void* d_out, int out_size) {
    (void)in_sizes; (void)n_in; (void)out_size;
    const float* x     = (const float*)d_in[0];  // [16,256,64,64]
    const float* w_qkv = (const float*)d_in[1];  // [1536,256]
    const float* w_out = (const float*)d_in[2];  // [256,512]
    const float* b_out = (const float*)d_in[3];  // [256]
    float* out = (float*)d_out;                  // [16,256,64,64]

    gram_kernel<<<dim3(4, NSPLIT, NB), 256>>>(x);
    reduce_g_kernel<<<NB * NC * NC / 4 / 256, 256>>>();
    gemm64_kernel<0><<<dim3(4, 8, NB), 256>>>(w_qkv);
    attn_kernel<<<dim3(NHEADS, NB), 256>>>(w_qkv);
    gemm64_kernel<1><<<dim3(4, 4, NB), 256>>>(w_out);
    final_kernel<<<dim3(32, 2, NB), 256>>>(x, b_out, out);
}